// round 7
// baseline (speedup 1.0000x reference)
#include <cuda_runtime.h>

#define B_SZ 256
#define T_SZ 2000
#define F_SZ 128

#define CHUNK   64                 // timesteps per pipeline chunk
#define NCHUNK  32                 // ceil(2000/64); last chunk has 16 valid
#define NBUF    4                  // smem ring depth
#define DOT_WARPS 8
#define T_PER_WARP 8               // rows per dot warp per chunk
#define NPASS   2                  // 4 rows per pass (8 lanes/row)
#define THREADS (32 * (DOT_WARPS + 1))  // 288: warp 0 = scan, warps 1..8 = dot

// BETA = sigmoid(2.0), VTH = 1.0
#define BETA_F 0.8807970779778823f

// named barriers: FULL(i) "buffer i produced", EMPTY(i) "buffer i free"
#define BAR_FULL(i)  (1 + (i))
#define BAR_EMPTY(i) (1 + NBUF + (i))

__device__ __forceinline__ void bar_sync(int id) {
    asm volatile("bar.sync %0, %1;" :: "r"(id), "n"(THREADS) : "memory");
}
__device__ __forceinline__ void bar_arrive(int id) {
    asm volatile("bar.arrive %0, %1;" :: "r"(id), "n"(THREADS) : "memory");
}

__global__ void __launch_bounds__(THREADS, 2) lif_fused_kernel(
    const float* __restrict__ x, const float* __restrict__ W,
    const float* __restrict__ bias, float* __restrict__ out, int out_size)
{
    __shared__ float cur_s[NBUF][CHUNK];

    const int b    = blockIdx.x;          // batch row
    const int wid  = threadIdx.x >> 5;
    const int lane = threadIdx.x & 31;

    if (wid > 0) {
        // ================= producers: dot warps 1..8 =================
        // 8 lanes per timestep-row, 4 rows per pass, 2 passes per chunk.
        const int sub = lane & 7;   // position within row (8 lanes x 16 floats)
        const int grp = lane >> 3;  // which of the 4 rows in this pass

        // W slice for this lane: float4 indices sub, sub+8, sub+16, sub+24
        float4 w4[4];
        #pragma unroll
        for (int j = 0; j < 4; ++j)
            w4[j] = reinterpret_cast<const float4*>(W)[sub + 8 * j];
        const float bias_v = bias[0];

        const int slice0 = (wid - 1) * T_PER_WARP;
        const float4* X4 = reinterpret_cast<const float4*>(
            x + (size_t)b * T_SZ * F_SZ);

        for (int c = 0; c < NCHUNK; ++c) {
            const int buf = c & (NBUF - 1);
            const int t0  = c * CHUNK + slice0;

            // Phase 1: batch ALL loads for this chunk (8 LDG.128/warp, regs only,
            // issued BEFORE the ring-slot wait so they overlap it).
            float4 xv[NPASS][4];
            #pragma unroll
            for (int p = 0; p < NPASS; ++p) {
                int trow = t0 + p * 4 + grp;
                trow = (trow < T_SZ) ? trow : (T_SZ - 1);   // clamp tail
                const float4* rp = X4 + (size_t)trow * (F_SZ / 4) + sub;
                #pragma unroll
                for (int j = 0; j < 4; ++j)
                    xv[p][j] = rp[8 * j];
            }

            bar_sync(BAR_EMPTY(buf));   // wait for ring slot

            // Phase 2: local dot (16 FFMA) + 3-stage 8-lane butterfly per pass
            #pragma unroll
            for (int p = 0; p < NPASS; ++p) {
                float s = 0.0f;
                #pragma unroll
                for (int j = 0; j < 4; ++j) {
                    s = fmaf(xv[p][j].x, w4[j].x, s);
                    s = fmaf(xv[p][j].y, w4[j].y, s);
                    s = fmaf(xv[p][j].z, w4[j].z, s);
                    s = fmaf(xv[p][j].w, w4[j].w, s);
                }
                s += __shfl_xor_sync(0xFFFFFFFFu, s, 4);
                s += __shfl_xor_sync(0xFFFFFFFFu, s, 2);
                s += __shfl_xor_sync(0xFFFFFFFFu, s, 1);

                const int trow = t0 + p * 4 + grp;
                if (sub == 0 && trow < T_SZ)
                    cur_s[buf][trow - c * CHUNK] = s + bias_v;
            }

            bar_arrive(BAR_FULL(buf));  // signal produced; roll on
        }
    } else {
        // ================= consumer: scan warp 0 =================
        #pragma unroll
        for (int i = 0; i < NBUF; ++i)
            bar_arrive(BAR_EMPTY(i));   // prime the ring

        float v = 0.0f;
        float* out_row = out + (size_t)b * T_SZ;

        for (int c = 0; c < NCHUNK; ++c) {
            const int buf = c & (NBUF - 1);

            bar_sync(BAR_FULL(buf));    // wait for all 8 producer arrivals

            if (lane == 0) {
                const int tbase = c * CHUNK;
                const int ngrp  = ((c == NCHUNK - 1) ? (T_SZ - tbase) : CHUNK) / 4;
                #pragma unroll 4
                for (int g = 0; g < ngrp; ++g) {
                    float4 cu4 = reinterpret_cast<const float4*>(
                        &cur_s[buf][g * 4])[0];
                    float4 spk4;
                    #pragma unroll
                    for (int k = 0; k < 4; ++k) {
                        float cu = ((const float*)&cu4)[k];
                        float u  = fmaf(BETA_F, v, cu);   // leaky integrate
                        float um = u - 1.0f;              // off critical path
                        bool  p  = (u >= 1.0f);           // threshold (VTH=1)
                        v = p ? um : u;                   // subtraction reset
                        ((float*)&spk4)[k] = p ? 1.0f : 0.0f;
                    }
                    reinterpret_cast<float4*>(out_row + tbase + g * 4)[0] = spk4;
                }
            }

            bar_arrive(BAR_EMPTY(buf)); // release ring slot
        }

        // final membrane potential vT
        if (lane == 0 && out_size > B_SZ * T_SZ)
            out[B_SZ * T_SZ + b] = v;
    }
}

extern "C" void kernel_launch(void* const* d_in, const int* in_sizes, int n_in,
                              void* d_out, int out_size)
{
    const float* x    = (const float*)d_in[0];  // [256, 2000, 128] fp32
    const float* W    = (const float*)d_in[1];  // [128, 1] fp32
    const float* bias = (const float*)d_in[2];  // [1] fp32
    float* out = (float*)d_out;                 // spikes [256*2000] then vT [256]

    lif_fused_kernel<<<B_SZ, THREADS>>>(x, W, bias, out, out_size);
}